// round 10
// baseline (speedup 1.0000x reference)
#include <cuda_runtime.h>
#include <math.h>

#define BATCH 64
#define SEQ   512
#define EMB   512
#define HID   1024

#define NCTA      128           // recurrence grid (<=148 -> all co-resident)
#define W_STRIDE  1028          // 1024 + 4 pad (bank-conflict break), float4-aligned
#define A_STRIDE  68            // 64 + 4 pad, float4-aligned
#define ABUF      (32 * A_STRIDE)
#define RNN_SMEM_FLOATS (16 * W_STRIDE + 2 * ABUF)
#define RNN_SMEM_BYTES  (RNN_SMEM_FLOATS * 4)

// ---------------- device scratch (static: no runtime allocation) ----------------
__device__ float    g_a[2][BATCH * HID];   // recurrent state, double buffered
__device__ unsigned g_bar;                 // grid barrier counter

// ---------------- kernel 0: per-launch init (graph replays must be deterministic) ----
__global__ void init_kernel() {
    int idx = blockIdx.x * blockDim.x + threadIdx.x;
    if (idx < BATCH * HID) g_a[0][idx] = 0.0f;
    if (idx == 0) g_bar = 0u;
}

// ---------------- kernel 1: xproj GEMM ----------------
// out[(s*64+b)*1024 + h] = sum_e X[b][s][e] * W_ax[h][e] + b_a[h]
// 128x128 tile, k-chunk 8, 256 threads, 8x8 microtile
__global__ __launch_bounds__(256, 2)
void xproj_kernel(const float* __restrict__ X, const float* __restrict__ Wax,
                  const float* __restrict__ ba, float* __restrict__ out)
{
    __shared__ float As[8][128];
    __shared__ float Bs[8][128];

    const int bm = blockIdx.y;          // 0..255
    const int bn = blockIdx.x;          // 0..7
    const int t  = threadIdx.x;
    const int tx = t & 15;
    const int ty = t >> 4;

    const int lrow = t >> 1;            // 0..127
    const int lkq  = (t & 1) * 4;       // 0 or 4

    // A row (m = s*64 + b): contiguous in e
    const int m  = bm * 128 + lrow;
    const int sA = m >> 6;
    const int bA = m & 63;
    const float* Arow = X + ((size_t)bA * SEQ + sA) * EMB;
    const float* Brow = Wax + (size_t)(bn * 128 + lrow) * EMB;

    float acc[8][8];
#pragma unroll
    for (int i = 0; i < 8; i++)
#pragma unroll
        for (int j = 0; j < 8; j++) acc[i][j] = 0.0f;

    for (int k0 = 0; k0 < EMB; k0 += 8) {
        float4 av = *(const float4*)(Arow + k0 + lkq);
        float4 bv = *(const float4*)(Brow + k0 + lkq);
        __syncthreads();
        As[lkq + 0][lrow] = av.x; As[lkq + 1][lrow] = av.y;
        As[lkq + 2][lrow] = av.z; As[lkq + 3][lrow] = av.w;
        Bs[lkq + 0][lrow] = bv.x; Bs[lkq + 1][lrow] = bv.y;
        Bs[lkq + 2][lrow] = bv.z; Bs[lkq + 3][lrow] = bv.w;
        __syncthreads();
#pragma unroll
        for (int k = 0; k < 8; k++) {
            float a_f[8], b_f[8];
            *(float4*)&a_f[0] = *(const float4*)&As[k][ty * 8];
            *(float4*)&a_f[4] = *(const float4*)&As[k][ty * 8 + 4];
            *(float4*)&b_f[0] = *(const float4*)&Bs[k][tx * 8];
            *(float4*)&b_f[4] = *(const float4*)&Bs[k][tx * 8 + 4];
#pragma unroll
            for (int i = 0; i < 8; i++)
#pragma unroll
                for (int j = 0; j < 8; j++)
                    acc[i][j] += a_f[i] * b_f[j];
        }
    }

    const int n0 = bn * 128 + tx * 8;
    const int m0 = bm * 128 + ty * 8;
    float4 bl = *(const float4*)(ba + n0);
    float4 bh = *(const float4*)(ba + n0 + 4);
#pragma unroll
    for (int i = 0; i < 8; i++) {
        size_t ro = (size_t)(m0 + i) * HID + n0;
        float4 o0 = make_float4(acc[i][0] + bl.x, acc[i][1] + bl.y,
                                acc[i][2] + bl.z, acc[i][3] + bl.w);
        float4 o1 = make_float4(acc[i][4] + bh.x, acc[i][5] + bh.y,
                                acc[i][6] + bh.z, acc[i][7] + bh.w);
        *(float4*)(out + ro)     = o0;
        *(float4*)(out + ro + 4) = o1;
    }
}

// ---------------- kernel 2: persistent recurrence ----------------
// 128 CTAs, 128 threads. CTA tile: 32 b x 16 h, W rows pinned in SMEM.
// out holds xproj on entry; overwritten in place with tanh outputs.
__global__ __launch_bounds__(128, 1)
void rnn_kernel(const float* __restrict__ Waa, float* __restrict__ out,
                float* __restrict__ hid)
{
    extern __shared__ float smem[];
    float* Wsm = smem;                      // 16 x W_STRIDE
    float* Asm = smem + 16 * W_STRIDE;      // 2 x 32 x A_STRIDE

    const int t   = threadIdx.x;
    const int cta = blockIdx.x;             // 0..127
    const int hg  = cta >> 1;               // 0..63
    const int bg  = cta & 1;                // 0..1
    const int h0  = hg * 16;
    const int b0  = bg * 32;

    const int th = t & 7;                   // h-pair select (0..7)
    const int tb = t >> 3;                  // b-pair select (0..15)
    const int hA = h0 + 2 * th;
    const int bA = b0 + 2 * tb;

    // pin this CTA's 16 W_aa rows in SMEM (once, reused for all 512 steps)
    for (int idx = t; idx < 16 * 256; idx += 128) {
        int r = idx >> 8, c4 = idx & 255;
        float4 v = *(const float4*)(Waa + (size_t)(h0 + r) * HID + c4 * 4);
        *(float4*)&Wsm[r * W_STRIDE + c4 * 4] = v;
    }
    __syncthreads();

    unsigned target = gridDim.x;

#pragma unroll 1
    for (int s = 0; s < SEQ; s++) {
        const float* acur = g_a[s & 1];
        float*       anxt = g_a[(s + 1) & 1];

        float acc00 = 0.f, acc01 = 0.f, acc10 = 0.f, acc11 = 0.f;

        // prologue: stage a-chunk 0 (32 b x 64 k)
        float4 pre[4];
#pragma unroll
        for (int j = 0; j < 4; j++) {
            int f = t + 128 * j, r = f >> 4, c4 = f & 15;
            pre[j] = *(const float4*)(acur + (size_t)(b0 + r) * HID + c4 * 4);
        }
#pragma unroll
        for (int j = 0; j < 4; j++) {
            int f = t + 128 * j, r = f >> 4, c4 = f & 15;
            *(float4*)&Asm[r * A_STRIDE + c4 * 4] = pre[j];
        }
        __syncthreads();

#pragma unroll 1
        for (int c = 0; c < 16; c++) {
            const int cb = c & 1;
            if (c < 15) {
                const int k0n = (c + 1) * 64;
#pragma unroll
                for (int j = 0; j < 4; j++) {
                    int f = t + 128 * j, r = f >> 4, c4 = f & 15;
                    pre[j] = *(const float4*)(acur + (size_t)(b0 + r) * HID + k0n + c4 * 4);
                }
            }
            const float* A0 = Asm + cb * ABUF + (2 * tb) * A_STRIDE;
            const float* A1 = A0 + A_STRIDE;
            const float* W0 = Wsm + (2 * th) * W_STRIDE + c * 64;
            const float* W1 = W0 + W_STRIDE;
#pragma unroll
            for (int kk = 0; kk < 16; kk++) {
                float4 a0 = *(const float4*)(A0 + kk * 4);
                float4 a1 = *(const float4*)(A1 + kk * 4);
                float4 w0 = *(const float4*)(W0 + kk * 4);
                float4 w1 = *(const float4*)(W1 + kk * 4);
                acc00 += a0.x * w0.x; acc00 += a0.y * w0.y;
                acc00 += a0.z * w0.z; acc00 += a0.w * w0.w;
                acc01 += a0.x * w1.x; acc01 += a0.y * w1.y;
                acc01 += a0.z * w1.z; acc01 += a0.w * w1.w;
                acc10 += a1.x * w0.x; acc10 += a1.y * w0.y;
                acc10 += a1.z * w0.z; acc10 += a1.w * w0.w;
                acc11 += a1.x * w1.x; acc11 += a1.y * w1.y;
                acc11 += a1.z * w1.z; acc11 += a1.w * w1.w;
            }
            if (c < 15) {
#pragma unroll
                for (int j = 0; j < 4; j++) {
                    int f = t + 128 * j, r = f >> 4, c4 = f & 15;
                    *(float4*)&Asm[(cb ^ 1) * ABUF + r * A_STRIDE + c4 * 4] = pre[j];
                }
            }
            __syncthreads();
        }

        // epilogue: tanh(acc + xproj), write outputs (in place) + next state
        {
            const size_t base = (size_t)s * (BATCH * HID);
            const int i00 = bA * HID + hA;
            float2 xp0 = *(const float2*)(out + base + i00);
            float2 xp1 = *(const float2*)(out + base + i00 + HID);
            float2 r0 = make_float2(tanhf(acc00 + xp0.x), tanhf(acc01 + xp0.y));
            float2 r1 = make_float2(tanhf(acc10 + xp1.x), tanhf(acc11 + xp1.y));
            *(float2*)(out + base + i00)       = r0;
            *(float2*)(out + base + i00 + HID) = r1;
            *(float2*)(anxt + i00)             = r0;
            *(float2*)(anxt + i00 + HID)       = r1;
            if (hid && s == SEQ - 1) {
                *(float2*)(hid + i00)       = r0;
                *(float2*)(hid + i00 + HID) = r1;
            }
        }

        // grid barrier (release/acquire through L2) — all 128 CTAs co-resident
        __threadfence();
        __syncthreads();
        if (t == 0) {
            asm volatile("red.release.gpu.add.u32 [%0], 1;" :: "l"(&g_bar) : "memory");
            unsigned v;
            do {
                asm volatile("ld.acquire.gpu.u32 %0, [%1];" : "=r"(v) : "l"(&g_bar) : "memory");
            } while (v < target);
        }
        __syncthreads();
        target += gridDim.x;
    }
}

// ---------------- host launcher ----------------
extern "C" void kernel_launch(void* const* d_in, const int* in_sizes, int n_in,
                              void* d_out, int out_size)
{
    // map inputs by element count (robust to ordering)
    const float *X = nullptr, *Wax = nullptr, *Waa = nullptr, *ba = nullptr;
    for (int i = 0; i < n_in; i++) {
        switch (in_sizes[i]) {
            case BATCH * SEQ * EMB: X   = (const float*)d_in[i]; break;
            case HID * EMB:         Wax = (const float*)d_in[i]; break;
            case HID * HID:         Waa = (const float*)d_in[i]; break;
            case HID:               ba  = (const float*)d_in[i]; break;
            default: break;
        }
    }
    if (!X || !Wax || !Waa || !ba) {       // fallback: positional
        X   = (const float*)d_in[0];
        Wax = (const float*)d_in[1];
        Waa = (const float*)d_in[2];
        ba  = (const float*)d_in[3];
    }

    const long long needOut = (long long)SEQ * BATCH * HID;           // outputs
    if ((long long)out_size < needOut) return;                        // unexpected layout
    float* outp = (float*)d_out;
    float* hidp = ((long long)out_size >= needOut + (long long)BATCH * HID)
                      ? outp + needOut : nullptr;

    cudaFuncSetAttribute(rnn_kernel, cudaFuncAttributeMaxDynamicSharedMemorySize,
                         RNN_SMEM_BYTES);

    init_kernel<<<256, 256>>>();
    xproj_kernel<<<dim3(8, 256), 256>>>(X, Wax, ba, outp);
    rnn_kernel<<<NCTA, 128, RNN_SMEM_BYTES>>>(Waa, outp, hidp);
}

// round 11
// speedup vs baseline: 1.0010x; 1.0010x over previous
#include <cuda_runtime.h>
#include <math.h>

#define BATCH 64
#define SEQ   512
#define EMB   512
#define HID   1024

#define NCTA      128           // recurrence grid (<=148 -> all co-resident)
#define W_STRIDE  1028          // 1024 + 4 pad (bank-conflict break), float4-aligned
#define A_STRIDE  68            // 64 + 4 pad, float4-aligned
#define ABUF      (32 * A_STRIDE)
#define RNN_SMEM_FLOATS (16 * W_STRIDE + 2 * ABUF)
#define RNN_SMEM_BYTES  (RNN_SMEM_FLOATS * 4)

// ---------------- device scratch (static: no runtime allocation) ----------------
__device__ float    g_a[2][BATCH * HID];   // recurrent state, double buffered
__device__ unsigned g_bar;                 // grid barrier counter

// ---------------- kernel 0: per-launch init (graph replays must be deterministic) ----
__global__ void init_kernel() {
    int idx = blockIdx.x * blockDim.x + threadIdx.x;
    if (idx < BATCH * HID) g_a[0][idx] = 0.0f;
    if (idx == 0) g_bar = 0u;
}

// ---------------- kernel 1: xproj GEMM ----------------
// out[(s*64+b)*1024 + h] = sum_e X[b][s][e] * W_ax[h][e] + b_a[h]
// 128x128 tile, k-chunk 8, 256 threads, 8x8 microtile
__global__ __launch_bounds__(256, 2)
void xproj_kernel(const float* __restrict__ X, const float* __restrict__ Wax,
                  const float* __restrict__ ba, float* __restrict__ out)
{
    __shared__ float As[8][128];
    __shared__ float Bs[8][128];

    const int bm = blockIdx.y;          // 0..255
    const int bn = blockIdx.x;          // 0..7
    const int t  = threadIdx.x;
    const int tx = t & 15;
    const int ty = t >> 4;

    const int lrow = t >> 1;            // 0..127
    const int lkq  = (t & 1) * 4;       // 0 or 4

    // A row (m = s*64 + b): contiguous in e
    const int m  = bm * 128 + lrow;
    const int sA = m >> 6;
    const int bA = m & 63;
    const float* Arow = X + ((size_t)bA * SEQ + sA) * EMB;
    const float* Brow = Wax + (size_t)(bn * 128 + lrow) * EMB;

    float acc[8][8];
#pragma unroll
    for (int i = 0; i < 8; i++)
#pragma unroll
        for (int j = 0; j < 8; j++) acc[i][j] = 0.0f;

    for (int k0 = 0; k0 < EMB; k0 += 8) {
        float4 av = *(const float4*)(Arow + k0 + lkq);
        float4 bv = *(const float4*)(Brow + k0 + lkq);
        __syncthreads();
        As[lkq + 0][lrow] = av.x; As[lkq + 1][lrow] = av.y;
        As[lkq + 2][lrow] = av.z; As[lkq + 3][lrow] = av.w;
        Bs[lkq + 0][lrow] = bv.x; Bs[lkq + 1][lrow] = bv.y;
        Bs[lkq + 2][lrow] = bv.z; Bs[lkq + 3][lrow] = bv.w;
        __syncthreads();
#pragma unroll
        for (int k = 0; k < 8; k++) {
            float a_f[8], b_f[8];
            *(float4*)&a_f[0] = *(const float4*)&As[k][ty * 8];
            *(float4*)&a_f[4] = *(const float4*)&As[k][ty * 8 + 4];
            *(float4*)&b_f[0] = *(const float4*)&Bs[k][tx * 8];
            *(float4*)&b_f[4] = *(const float4*)&Bs[k][tx * 8 + 4];
#pragma unroll
            for (int i = 0; i < 8; i++)
#pragma unroll
                for (int j = 0; j < 8; j++)
                    acc[i][j] += a_f[i] * b_f[j];
        }
    }

    const int n0 = bn * 128 + tx * 8;
    const int m0 = bm * 128 + ty * 8;
    float4 bl = *(const float4*)(ba + n0);
    float4 bh = *(const float4*)(ba + n0 + 4);
#pragma unroll
    for (int i = 0; i < 8; i++) {
        size_t ro = (size_t)(m0 + i) * HID + n0;
        float4 o0 = make_float4(acc[i][0] + bl.x, acc[i][1] + bl.y,
                                acc[i][2] + bl.z, acc[i][3] + bl.w);
        float4 o1 = make_float4(acc[i][4] + bh.x, acc[i][5] + bh.y,
                                acc[i][6] + bh.z, acc[i][7] + bh.w);
        *(float4*)(out + ro)     = o0;
        *(float4*)(out + ro + 4) = o1;
    }
}

// ---------------- kernel 2: persistent recurrence ----------------
// 128 CTAs, 128 threads. CTA tile: 32 b x 16 h, W rows pinned in SMEM.
// out holds xproj on entry; overwritten in place with tanh outputs.
__global__ __launch_bounds__(128, 1)
void rnn_kernel(const float* __restrict__ Waa, float* __restrict__ out,
                float* __restrict__ hid)
{
    extern __shared__ float smem[];
    float* Wsm = smem;                      // 16 x W_STRIDE
    float* Asm = smem + 16 * W_STRIDE;      // 2 x 32 x A_STRIDE

    const int t   = threadIdx.x;
    const int cta = blockIdx.x;             // 0..127
    const int hg  = cta >> 1;               // 0..63
    const int bg  = cta & 1;                // 0..1
    const int h0  = hg * 16;
    const int b0  = bg * 32;

    const int th = t & 7;                   // h-pair select (0..7)
    const int tb = t >> 3;                  // b-pair select (0..15)
    const int hA = h0 + 2 * th;
    const int bA = b0 + 2 * tb;

    // pin this CTA's 16 W_aa rows in SMEM (once, reused for all 512 steps)
    for (int idx = t; idx < 16 * 256; idx += 128) {
        int r = idx >> 8, c4 = idx & 255;
        float4 v = *(const float4*)(Waa + (size_t)(h0 + r) * HID + c4 * 4);
        *(float4*)&Wsm[r * W_STRIDE + c4 * 4] = v;
    }
    __syncthreads();

    unsigned target = gridDim.x;

#pragma unroll 1
    for (int s = 0; s < SEQ; s++) {
        const float* acur = g_a[s & 1];
        float*       anxt = g_a[(s + 1) & 1];

        float acc00 = 0.f, acc01 = 0.f, acc10 = 0.f, acc11 = 0.f;

        // prologue: stage a-chunk 0 (32 b x 64 k)
        float4 pre[4];
#pragma unroll
        for (int j = 0; j < 4; j++) {
            int f = t + 128 * j, r = f >> 4, c4 = f & 15;
            pre[j] = *(const float4*)(acur + (size_t)(b0 + r) * HID + c4 * 4);
        }
#pragma unroll
        for (int j = 0; j < 4; j++) {
            int f = t + 128 * j, r = f >> 4, c4 = f & 15;
            *(float4*)&Asm[r * A_STRIDE + c4 * 4] = pre[j];
        }
        __syncthreads();

#pragma unroll 1
        for (int c = 0; c < 16; c++) {
            const int cb = c & 1;
            if (c < 15) {
                const int k0n = (c + 1) * 64;
#pragma unroll
                for (int j = 0; j < 4; j++) {
                    int f = t + 128 * j, r = f >> 4, c4 = f & 15;
                    pre[j] = *(const float4*)(acur + (size_t)(b0 + r) * HID + k0n + c4 * 4);
                }
            }
            const float* A0 = Asm + cb * ABUF + (2 * tb) * A_STRIDE;
            const float* A1 = A0 + A_STRIDE;
            const float* W0 = Wsm + (2 * th) * W_STRIDE + c * 64;
            const float* W1 = W0 + W_STRIDE;
#pragma unroll
            for (int kk = 0; kk < 16; kk++) {
                float4 a0 = *(const float4*)(A0 + kk * 4);
                float4 a1 = *(const float4*)(A1 + kk * 4);
                float4 w0 = *(const float4*)(W0 + kk * 4);
                float4 w1 = *(const float4*)(W1 + kk * 4);
                acc00 += a0.x * w0.x; acc00 += a0.y * w0.y;
                acc00 += a0.z * w0.z; acc00 += a0.w * w0.w;
                acc01 += a0.x * w1.x; acc01 += a0.y * w1.y;
                acc01 += a0.z * w1.z; acc01 += a0.w * w1.w;
                acc10 += a1.x * w0.x; acc10 += a1.y * w0.y;
                acc10 += a1.z * w0.z; acc10 += a1.w * w0.w;
                acc11 += a1.x * w1.x; acc11 += a1.y * w1.y;
                acc11 += a1.z * w1.z; acc11 += a1.w * w1.w;
            }
            if (c < 15) {
#pragma unroll
                for (int j = 0; j < 4; j++) {
                    int f = t + 128 * j, r = f >> 4, c4 = f & 15;
                    *(float4*)&Asm[(cb ^ 1) * ABUF + r * A_STRIDE + c4 * 4] = pre[j];
                }
            }
            __syncthreads();
        }

        // epilogue: tanh(acc + xproj), write outputs (in place) + next state
        {
            const size_t base = (size_t)s * (BATCH * HID);
            const int i00 = bA * HID + hA;
            float2 xp0 = *(const float2*)(out + base + i00);
            float2 xp1 = *(const float2*)(out + base + i00 + HID);
            float2 r0 = make_float2(tanhf(acc00 + xp0.x), tanhf(acc01 + xp0.y));
            float2 r1 = make_float2(tanhf(acc10 + xp1.x), tanhf(acc11 + xp1.y));
            *(float2*)(out + base + i00)       = r0;
            *(float2*)(out + base + i00 + HID) = r1;
            *(float2*)(anxt + i00)             = r0;
            *(float2*)(anxt + i00 + HID)       = r1;
            if (hid && s == SEQ - 1) {
                *(float2*)(hid + i00)       = r0;
                *(float2*)(hid + i00 + HID) = r1;
            }
        }

        // grid barrier (release/acquire through L2) — all 128 CTAs co-resident
        __threadfence();
        __syncthreads();
        if (t == 0) {
            asm volatile("red.release.gpu.add.u32 [%0], 1;" :: "l"(&g_bar) : "memory");
            unsigned v;
            do {
                asm volatile("ld.acquire.gpu.u32 %0, [%1];" : "=r"(v) : "l"(&g_bar) : "memory");
            } while (v < target);
        }
        __syncthreads();
        target += gridDim.x;
    }
}

// ---------------- host launcher ----------------
extern "C" void kernel_launch(void* const* d_in, const int* in_sizes, int n_in,
                              void* d_out, int out_size)
{
    // map inputs by element count (robust to ordering)
    const float *X = nullptr, *Wax = nullptr, *Waa = nullptr, *ba = nullptr;
    for (int i = 0; i < n_in; i++) {
        switch (in_sizes[i]) {
            case BATCH * SEQ * EMB: X   = (const float*)d_in[i]; break;
            case HID * EMB:         Wax = (const float*)d_in[i]; break;
            case HID * HID:         Waa = (const float*)d_in[i]; break;
            case HID:               ba  = (const float*)d_in[i]; break;
            default: break;
        }
    }
    if (!X || !Wax || !Waa || !ba) {       // fallback: positional
        X   = (const float*)d_in[0];
        Wax = (const float*)d_in[1];
        Waa = (const float*)d_in[2];
        ba  = (const float*)d_in[3];
    }

    const long long needOut = (long long)SEQ * BATCH * HID;           // outputs
    if ((long long)out_size < needOut) return;                        // unexpected layout
    float* outp = (float*)d_out;
    float* hidp = ((long long)out_size >= needOut + (long long)BATCH * HID)
                      ? outp + needOut : nullptr;

    cudaFuncSetAttribute(rnn_kernel, cudaFuncAttributeMaxDynamicSharedMemorySize,
                         RNN_SMEM_BYTES);

    init_kernel<<<256, 256>>>();
    xproj_kernel<<<dim3(8, 256), 256>>>(X, Wax, ba, outp);
    rnn_kernel<<<NCTA, 128, RNN_SMEM_BYTES>>>(Waa, outp, hidp);
}

// round 12
// speedup vs baseline: 1.6608x; 1.6592x over previous
#include <cuda_runtime.h>
#include <math.h>

#define BATCH 64
#define SEQ   512
#define EMB   512
#define HID   1024
#define BH    (BATCH * HID)
#define SBH   (SEQ * BATCH * HID)

// ---- recurrence decomposition: 16 h-tiles x 8 k-splits = 128 CTAs ----
#define NH   16            // h-tiles
#define NK   8             // k-splits
#define HT   64            // h per tile
#define KT   128           // k per split
#define KB   (KT / 4)      // 32 k-blocks of 4 floats
#define NCTA (NH * NK)     // 128 (<=148 -> all co-resident, 1 CTA/SM)

// smem: Wsm[HT][KT] (32KB) + Asm[BATCH][KT] swizzled (32KB)
#define RNN_SMEM_BYTES ((HT * KT + BATCH * KT) * 4)

// ---------------- device scratch (static: no runtime allocation) ----------------
__device__ float    g_part[2][NCTA][BATCH * HT];   // k-split partials, double buffered (4MB)
__device__ unsigned g_pdone[NH * 32];              // per h-group partial-done counters (padded)
__device__ unsigned g_adone[NH * 32];              // per h-group a-slice-done counters (padded)

// ---------------- kernel 0: per-launch init ----------------
__global__ void init_kernel() {
    int i = blockIdx.x * blockDim.x + threadIdx.x;
    if (i < NH * 32) { g_pdone[i] = 0u; g_adone[i] = 0u; }
}

// ---------------- kernel 1: xproj GEMM (unchanged, known-good) ----------------
__global__ __launch_bounds__(256, 2)
void xproj_kernel(const float* __restrict__ X, const float* __restrict__ Wax,
                  const float* __restrict__ ba, float* __restrict__ out)
{
    __shared__ float As[8][128];
    __shared__ float Bs[8][128];

    const int bm = blockIdx.y;
    const int bn = blockIdx.x;
    const int t  = threadIdx.x;
    const int tx = t & 15;
    const int ty = t >> 4;

    const int lrow = t >> 1;
    const int lkq  = (t & 1) * 4;

    const int m  = bm * 128 + lrow;
    const int sA = m >> 6;
    const int bA = m & 63;
    const float* Arow = X + ((size_t)bA * SEQ + sA) * EMB;
    const float* Brow = Wax + (size_t)(bn * 128 + lrow) * EMB;

    float acc[8][8];
#pragma unroll
    for (int i = 0; i < 8; i++)
#pragma unroll
        for (int j = 0; j < 8; j++) acc[i][j] = 0.0f;

    for (int k0 = 0; k0 < EMB; k0 += 8) {
        float4 av = *(const float4*)(Arow + k0 + lkq);
        float4 bv = *(const float4*)(Brow + k0 + lkq);
        __syncthreads();
        As[lkq + 0][lrow] = av.x; As[lkq + 1][lrow] = av.y;
        As[lkq + 2][lrow] = av.z; As[lkq + 3][lrow] = av.w;
        Bs[lkq + 0][lrow] = bv.x; Bs[lkq + 1][lrow] = bv.y;
        Bs[lkq + 2][lrow] = bv.z; Bs[lkq + 3][lrow] = bv.w;
        __syncthreads();
#pragma unroll
        for (int k = 0; k < 8; k++) {
            float a_f[8], b_f[8];
            *(float4*)&a_f[0] = *(const float4*)&As[k][ty * 8];
            *(float4*)&a_f[4] = *(const float4*)&As[k][ty * 8 + 4];
            *(float4*)&b_f[0] = *(const float4*)&Bs[k][tx * 8];
            *(float4*)&b_f[4] = *(const float4*)&Bs[k][tx * 8 + 4];
#pragma unroll
            for (int i = 0; i < 8; i++)
#pragma unroll
                for (int j = 0; j < 8; j++)
                    acc[i][j] += a_f[i] * b_f[j];
        }
    }

    const int n0 = bn * 128 + tx * 8;
    const int m0 = bm * 128 + ty * 8;
    float4 bl = *(const float4*)(ba + n0);
    float4 bh = *(const float4*)(ba + n0 + 4);
#pragma unroll
    for (int i = 0; i < 8; i++) {
        size_t ro = (size_t)(m0 + i) * HID + n0;
        float4 o0 = make_float4(acc[i][0] + bl.x, acc[i][1] + bl.y,
                                acc[i][2] + bl.z, acc[i][3] + bl.w);
        float4 o1 = make_float4(acc[i][4] + bh.x, acc[i][5] + bh.y,
                                acc[i][6] + bh.z, acc[i][7] + bh.w);
        *(float4*)(out + ro)     = o0;
        *(float4*)(out + ro + 4) = o1;
    }
}

// ---------------- packed fp32 helpers ----------------
__device__ __forceinline__ void ffma2(unsigned long long& acc,
                                      unsigned long long a, unsigned long long w) {
    asm("fma.rn.f32x2 %0, %1, %2, %0;" : "+l"(acc) : "l"(a), "l"(w));
}
__device__ __forceinline__ float fsum2(unsigned long long a) {
    float lo, hi;
    asm("mov.b64 {%0,%1}, %2;" : "=f"(lo), "=f"(hi) : "l"(a));
    return lo + hi;
}

// ---------------- kernel 2: persistent recurrence ----------------
// CTA (H,K): GEMM partial over k-split K for h-tile H (64b x 64h x 128k),
// then group-local reduce of its 8-b-row slice. Sync via per-group counters.
__global__ __launch_bounds__(128, 1)
void rnn_kernel(const float* __restrict__ Waa, float* __restrict__ out,
                float* __restrict__ hid)
{
    extern __shared__ float smem[];
    float* Wsm = smem;             // [HT][KT], plain layout
    float* Asm = smem + HT * KT;   // [BATCH][KT], k-block xor-swizzled by (b>>3)

    const int t   = threadIdx.x;
    const int cta = blockIdx.x;
    const int H   = cta >> 3;      // h-tile 0..15
    const int K   = cta & 7;       // k-split 0..7
    const int h0  = H * HT;
    const int k0  = K * KT;

    const int bg = t & 7;          // 8 b-groups (8 rows each)
    const int hg = t >> 3;         // 16 h-groups (4 rows each)

    // stage this CTA's W tile once (reused for all 512 steps)
    for (int idx = t; idx < HT * KB; idx += 128) {
        int h = idx >> 5, kb = idx & 31;
        float4 v = *(const float4*)(Waa + (size_t)(h0 + h) * HID + k0 + kb * 4);
        *(float4*)(Wsm + h * KT + kb * 4) = v;
    }
    __syncthreads();

    // reduce-slice coordinates (this CTA reduces b-rows [8K, 8K+8) of tile H)
    const int rb  = 8 * K + (t >> 4);    // global batch row
    const int rhl = 4 * (t & 15);        // local h within tile

    unsigned long long acc[8][4];

#pragma unroll 1
    for (int s = 0; s < SEQ; s++) {
        if (s > 0) {
            // wait: a-columns ready (producer groups 2K, 2K+1) + own-group WAR
            if (t == 0) {
                const unsigned tgt = 8u * (unsigned)s;
                unsigned v;
                do { asm volatile("ld.acquire.gpu.u32 %0,[%1];" : "=r"(v) : "l"(g_adone + (2 * K) * 32)); } while (v < tgt);
                do { asm volatile("ld.acquire.gpu.u32 %0,[%1];" : "=r"(v) : "l"(g_adone + (2 * K + 1) * 32)); } while (v < tgt);
                do { asm volatile("ld.acquire.gpu.u32 %0,[%1];" : "=r"(v) : "l"(g_adone + H * 32)); } while (v < tgt);
            }
            __syncthreads();

            // stage A = out[s-1][b][k0 .. k0+127], swizzled
            const float* aprev = out + (size_t)(s - 1) * BH;
#pragma unroll
            for (int j = 0; j < (BATCH * KB) / 128; j++) {
                int idx = t + 128 * j;
                int b = idx >> 5, kb = idx & 31;
                float4 v = *(const float4*)(aprev + (size_t)b * HID + k0 + kb * 4);
                *(float4*)(Asm + b * KT + ((kb ^ (b >> 3)) * 4)) = v;
            }
            __syncthreads();

#pragma unroll
            for (int i = 0; i < 8; i++)
#pragma unroll
                for (int j = 0; j < 4; j++) acc[i][j] = 0ull;

            const float* Abase = Asm + (bg * 8) * KT;
            const float* Wbase = Wsm + (hg * 4) * KT;

#pragma unroll 4
            for (int kb = 0; kb < KB; kb++) {
                const int slot = (kb ^ bg) * 4;
                ulonglong2 av[8], wv[4];
#pragma unroll
                for (int i = 0; i < 8; i++)
                    av[i] = *(const ulonglong2*)(Abase + i * KT + slot);
#pragma unroll
                for (int j = 0; j < 4; j++)
                    wv[j] = *(const ulonglong2*)(Wbase + j * KT + kb * 4);
#pragma unroll
                for (int i = 0; i < 8; i++)
#pragma unroll
                    for (int j = 0; j < 4; j++) {
                        ffma2(acc[i][j], av[i].x, wv[j].x);
                        ffma2(acc[i][j], av[i].y, wv[j].y);
                    }
            }

            // write partials for this k-split
            {
                float* P = g_part[s & 1][cta] + (bg * 8) * HT + hg * 4;
#pragma unroll
                for (int i = 0; i < 8; i++) {
                    float4 r = make_float4(fsum2(acc[i][0]), fsum2(acc[i][1]),
                                           fsum2(acc[i][2]), fsum2(acc[i][3]));
                    *(float4*)(P + i * HT) = r;
                }
            }
            __syncthreads();
            if (t == 0) {
                asm volatile("red.release.gpu.add.u32 [%0],1;" :: "l"(g_pdone + H * 32) : "memory");
                const unsigned tgt = 8u * (unsigned)s;
                unsigned v;
                do { asm volatile("ld.acquire.gpu.u32 %0,[%1];" : "=r"(v) : "l"(g_pdone + H * 32)); } while (v < tgt);
            }
            __syncthreads();
        }

        // ---- reduce: out[s] = tanh(xproj + sum_ks partial), 4 outputs/thread ----
        {
            float* orow = out + (size_t)s * BH + (size_t)rb * HID + h0 + rhl;
            float4 x = *(float4*)orow;
            if (s > 0) {
                const float* Pb = &g_part[s & 1][H * 8][rb * HT + rhl];
#pragma unroll
                for (int ks = 0; ks < 8; ks++) {
                    float4 p = *(const float4*)(Pb + ks * (BATCH * HT));
                    x.x += p.x; x.y += p.y; x.z += p.z; x.w += p.w;
                }
            }
            x.x = tanhf(x.x); x.y = tanhf(x.y);
            x.z = tanhf(x.z); x.w = tanhf(x.w);
            *(float4*)orow = x;
            if (hid && s == SEQ - 1)
                *(float4*)(hid + (size_t)rb * HID + h0 + rhl) = x;
        }
        __syncthreads();
        if (t == 0)
            asm volatile("red.release.gpu.add.u32 [%0],1;" :: "l"(g_adone + H * 32) : "memory");
    }
}

// ---------------- host launcher ----------------
extern "C" void kernel_launch(void* const* d_in, const int* in_sizes, int n_in,
                              void* d_out, int out_size)
{
    const float *X = nullptr, *Wax = nullptr, *Waa = nullptr, *ba = nullptr;
    for (int i = 0; i < n_in; i++) {
        switch (in_sizes[i]) {
            case BATCH * SEQ * EMB: X   = (const float*)d_in[i]; break;
            case HID * EMB:         Wax = (const float*)d_in[i]; break;
            case HID * HID:         Waa = (const float*)d_in[i]; break;
            case HID:               ba  = (const float*)d_in[i]; break;
            default: break;
        }
    }
    if (!X || !Wax || !Waa || !ba) {
        X   = (const float*)d_in[0];
        Wax = (const float*)d_in[1];
        Waa = (const float*)d_in[2];
        ba  = (const float*)d_in[3];
    }

    const long long needOut = (long long)SBH;
    if ((long long)out_size < needOut) return;
    float* outp = (float*)d_out;
    float* hidp = ((long long)out_size >= needOut + (long long)BH)
                      ? outp + needOut : nullptr;

    cudaFuncSetAttribute(rnn_kernel, cudaFuncAttributeMaxDynamicSharedMemorySize,
                         RNN_SMEM_BYTES);

    init_kernel<<<2, 256>>>();
    xproj_kernel<<<dim3(8, 256), 256>>>(X, Wax, ba, outp);
    rnn_kernel<<<NCTA, 128, RNN_SMEM_BYTES>>>(Waa, outp, hidp);
}

// round 15
// speedup vs baseline: 1.6616x; 1.0005x over previous
#include <cuda_runtime.h>
#include <math.h>

#define BATCH 64
#define SEQ   512
#define EMB   512
#define HID   1024
#define BH    (BATCH * HID)
#define SBH   (SEQ * BATCH * HID)

// ---- recurrence decomposition: 16 h-tiles x 8 k-splits = 128 CTAs ----
#define NH   16            // h-tiles
#define NK   8             // k-splits
#define HT   64            // h per tile
#define KT   128           // k per split
#define KB   (KT / 4)      // 32 k-blocks of 4 floats
#define NCTA (NH * NK)     // 128 (<=148 -> all co-resident, 1 CTA/SM)

// smem: Wsm[HT][KT] (32KB) + Asm[BATCH][KT] swizzled (32KB)
#define RNN_SMEM_BYTES ((HT * KT + BATCH * KT) * 4)

// ---------------- device scratch (static: no runtime allocation) ----------------
__device__ float    g_part[2][NCTA][BATCH * HT];   // k-split partials, double buffered (4MB)
__device__ unsigned g_pdone[NH * 32];              // per h-group partial-done counters (padded)
__device__ unsigned g_adone[NH * 32];              // per h-group a-slice-done counters (padded)

// ---------------- kernel 0: per-launch init ----------------
__global__ void init_kernel() {
    int i = blockIdx.x * blockDim.x + threadIdx.x;
    if (i < NH * 32) { g_pdone[i] = 0u; g_adone[i] = 0u; }
}

// ---------------- kernel 1: xproj GEMM (unchanged, known-good) ----------------
__global__ __launch_bounds__(256, 2)
void xproj_kernel(const float* __restrict__ X, const float* __restrict__ Wax,
                  const float* __restrict__ ba, float* __restrict__ out)
{
    __shared__ float As[8][128];
    __shared__ float Bs[8][128];

    const int bm = blockIdx.y;
    const int bn = blockIdx.x;
    const int t  = threadIdx.x;
    const int tx = t & 15;
    const int ty = t >> 4;

    const int lrow = t >> 1;
    const int lkq  = (t & 1) * 4;

    const int m  = bm * 128 + lrow;
    const int sA = m >> 6;
    const int bA = m & 63;
    const float* Arow = X + ((size_t)bA * SEQ + sA) * EMB;
    const float* Brow = Wax + (size_t)(bn * 128 + lrow) * EMB;

    float acc[8][8];
#pragma unroll
    for (int i = 0; i < 8; i++)
#pragma unroll
        for (int j = 0; j < 8; j++) acc[i][j] = 0.0f;

    for (int k0 = 0; k0 < EMB; k0 += 8) {
        float4 av = *(const float4*)(Arow + k0 + lkq);
        float4 bv = *(const float4*)(Brow + k0 + lkq);
        __syncthreads();
        As[lkq + 0][lrow] = av.x; As[lkq + 1][lrow] = av.y;
        As[lkq + 2][lrow] = av.z; As[lkq + 3][lrow] = av.w;
        Bs[lkq + 0][lrow] = bv.x; Bs[lkq + 1][lrow] = bv.y;
        Bs[lkq + 2][lrow] = bv.z; Bs[lkq + 3][lrow] = bv.w;
        __syncthreads();
#pragma unroll
        for (int k = 0; k < 8; k++) {
            float a_f[8], b_f[8];
            *(float4*)&a_f[0] = *(const float4*)&As[k][ty * 8];
            *(float4*)&a_f[4] = *(const float4*)&As[k][ty * 8 + 4];
            *(float4*)&b_f[0] = *(const float4*)&Bs[k][tx * 8];
            *(float4*)&b_f[4] = *(const float4*)&Bs[k][tx * 8 + 4];
#pragma unroll
            for (int i = 0; i < 8; i++)
#pragma unroll
                for (int j = 0; j < 8; j++)
                    acc[i][j] += a_f[i] * b_f[j];
        }
    }

    const int n0 = bn * 128 + tx * 8;
    const int m0 = bm * 128 + ty * 8;
    float4 bl = *(const float4*)(ba + n0);
    float4 bh = *(const float4*)(ba + n0 + 4);
#pragma unroll
    for (int i = 0; i < 8; i++) {
        size_t ro = (size_t)(m0 + i) * HID + n0;
        float4 o0 = make_float4(acc[i][0] + bl.x, acc[i][1] + bl.y,
                                acc[i][2] + bl.z, acc[i][3] + bl.w);
        float4 o1 = make_float4(acc[i][4] + bh.x, acc[i][5] + bh.y,
                                acc[i][6] + bh.z, acc[i][7] + bh.w);
        *(float4*)(out + ro)     = o0;
        *(float4*)(out + ro + 4) = o1;
    }
}

// ---------------- packed fp32 helpers ----------------
__device__ __forceinline__ void ffma2(unsigned long long& acc,
                                      unsigned long long a, unsigned long long w) {
    asm("fma.rn.f32x2 %0, %1, %2, %0;" : "+l"(acc) : "l"(a), "l"(w));
}
__device__ __forceinline__ float fsum2(unsigned long long a) {
    float lo, hi;
    asm("mov.b64 {%0,%1}, %2;" : "=f"(lo), "=f"(hi) : "l"(a));
    return lo + hi;
}

// ---------------- kernel 2: persistent recurrence ----------------
// CTA (H,K): GEMM partial over k-split K for h-tile H (64b x 64h x 128k),
// then group-local reduce of its 8-b-row slice. Sync via per-group counters.
__global__ __launch_bounds__(128, 1)
void rnn_kernel(const float* __restrict__ Waa, float* __restrict__ out,
                float* __restrict__ hid)
{
    extern __shared__ float smem[];
    float* Wsm = smem;             // [HT][KT], plain layout
    float* Asm = smem + HT * KT;   // [BATCH][KT], k-block xor-swizzled by (b>>3)

    const int t   = threadIdx.x;
    const int cta = blockIdx.x;
    const int H   = cta >> 3;      // h-tile 0..15
    const int K   = cta & 7;       // k-split 0..7
    const int h0  = H * HT;
    const int k0  = K * KT;

    const int bg = t & 7;          // 8 b-groups (8 rows each)
    const int hg = t >> 3;         // 16 h-groups (4 rows each)

    // stage this CTA's W tile once (reused for all 512 steps)
    for (int idx = t; idx < HT * KB; idx += 128) {
        int h = idx >> 5, kb = idx & 31;
        float4 v = *(const float4*)(Waa + (size_t)(h0 + h) * HID + k0 + kb * 4);
        *(float4*)(Wsm + h * KT + kb * 4) = v;
    }
    __syncthreads();

    // reduce-slice coordinates (this CTA reduces b-rows [8K, 8K+8) of tile H)
    const int rb  = 8 * K + (t >> 4);    // global batch row
    const int rhl = 4 * (t & 15);        // local h within tile

    unsigned long long acc[8][4];

#pragma unroll 1
    for (int s = 0; s < SEQ; s++) {
        if (s > 0) {
            // wait: a-columns ready (producer groups 2K, 2K+1) + own-group WAR
            if (t == 0) {
                const unsigned tgt = 8u * (unsigned)s;
                unsigned v;
                do { asm volatile("ld.acquire.gpu.u32 %0,[%1];" : "=r"(v) : "l"(g_adone + (2 * K) * 32)); } while (v < tgt);
                do { asm volatile("ld.acquire.gpu.u32 %0,[%1];" : "=r"(v) : "l"(g_adone + (2 * K + 1) * 32)); } while (v < tgt);
                do { asm volatile("ld.acquire.gpu.u32 %0,[%1];" : "=r"(v) : "l"(g_adone + H * 32)); } while (v < tgt);
            }
            __syncthreads();

            // stage A = out[s-1][b][k0 .. k0+127], swizzled
            const float* aprev = out + (size_t)(s - 1) * BH;
#pragma unroll
            for (int j = 0; j < (BATCH * KB) / 128; j++) {
                int idx = t + 128 * j;
                int b = idx >> 5, kb = idx & 31;
                float4 v = *(const float4*)(aprev + (size_t)b * HID + k0 + kb * 4);
                *(float4*)(Asm + b * KT + ((kb ^ (b >> 3)) * 4)) = v;
            }
            __syncthreads();

#pragma unroll
            for (int i = 0; i < 8; i++)
#pragma unroll
                for (int j = 0; j < 4; j++) acc[i][j] = 0ull;

            const float* Abase = Asm + (bg * 8) * KT;
            const float* Wbase = Wsm + (hg * 4) * KT;

#pragma unroll 4
            for (int kb = 0; kb < KB; kb++) {
                const int slot = (kb ^ bg) * 4;
                ulonglong2 av[8], wv[4];
#pragma unroll
                for (int i = 0; i < 8; i++)
                    av[i] = *(const ulonglong2*)(Abase + i * KT + slot);
#pragma unroll
                for (int j = 0; j < 4; j++)
                    wv[j] = *(const ulonglong2*)(Wbase + j * KT + kb * 4);
#pragma unroll
                for (int i = 0; i < 8; i++)
#pragma unroll
                    for (int j = 0; j < 4; j++) {
                        ffma2(acc[i][j], av[i].x, wv[j].x);
                        ffma2(acc[i][j], av[i].y, wv[j].y);
                    }
            }

            // write partials for this k-split
            {
                float* P = g_part[s & 1][cta] + (bg * 8) * HT + hg * 4;
#pragma unroll
                for (int i = 0; i < 8; i++) {
                    float4 r = make_float4(fsum2(acc[i][0]), fsum2(acc[i][1]),
                                           fsum2(acc[i][2]), fsum2(acc[i][3]));
                    *(float4*)(P + i * HT) = r;
                }
            }
            __syncthreads();
            if (t == 0) {
                asm volatile("red.release.gpu.add.u32 [%0],1;" :: "l"(g_pdone + H * 32) : "memory");
                const unsigned tgt = 8u * (unsigned)s;
                unsigned v;
                do { asm volatile("ld.acquire.gpu.u32 %0,[%1];" : "=r"(v) : "l"(g_pdone + H * 32)); } while (v < tgt);
            }
            __syncthreads();
        }

        // ---- reduce: out[s] = tanh(xproj + sum_ks partial), 4 outputs/thread ----
        {
            float* orow = out + (size_t)s * BH + (size_t)rb * HID + h0 + rhl;
            float4 x = *(float4*)orow;
            if (s > 0) {
                const float* Pb = &g_part[s & 1][H * 8][rb * HT + rhl];
#pragma unroll
                for (int ks = 0; ks < 8; ks++) {
                    float4 p = *(const float4*)(Pb + ks * (BATCH * HT));
                    x.x += p.x; x.y += p.y; x.z += p.z; x.w += p.w;
                }
            }
            x.x = tanhf(x.x); x.y = tanhf(x.y);
            x.z = tanhf(x.z); x.w = tanhf(x.w);
            *(float4*)orow = x;
            if (hid && s == SEQ - 1)
                *(float4*)(hid + (size_t)rb * HID + h0 + rhl) = x;
        }
        __syncthreads();
        if (t == 0)
            asm volatile("red.release.gpu.add.u32 [%0],1;" :: "l"(g_adone + H * 32) : "memory");
    }
}

// ---------------- host launcher ----------------
extern "C" void kernel_launch(void* const* d_in, const int* in_sizes, int n_in,
                              void* d_out, int out_size)
{
    const float *X = nullptr, *Wax = nullptr, *Waa = nullptr, *ba = nullptr;
    for (int i = 0; i < n_in; i++) {
        switch (in_sizes[i]) {
            case BATCH * SEQ * EMB: X   = (const float*)d_in[i]; break;
            case HID * EMB:         Wax = (const float*)d_in[i]; break;
            case HID * HID:         Waa = (const float*)d_in[i]; break;
            case HID:               ba  = (const float*)d_in[i]; break;
            default: break;
        }
    }
    if (!X || !Wax || !Waa || !ba) {
        X   = (const float*)d_in[0];
        Wax = (const float*)d_in[1];
        Waa = (const float*)d_in[2];
        ba  = (const float*)d_in[3];
    }

    const long long needOut = (long long)SBH;
    if ((long long)out_size < needOut) return;
    float* outp = (float*)d_out;
    float* hidp = ((long long)out_size >= needOut + (long long)BH)
                      ? outp + needOut : nullptr;

    cudaFuncSetAttribute(rnn_kernel, cudaFuncAttributeMaxDynamicSharedMemorySize,
                         RNN_SMEM_BYTES);

    init_kernel<<<2, 256>>>();
    xproj_kernel<<<dim3(8, 256), 256>>>(X, Wax, ba, outp);
    rnn_kernel<<<NCTA, 128, RNN_SMEM_BYTES>>>(Waa, outp, hidp);
}